// round 10
// baseline (speedup 1.0000x reference)
#include <cuda_runtime.h>

namespace {

constexpr int T  = 4096;
constexpr int H  = 16;
constexpr int P  = 64;    // d_head
constexpr int N  = 128;   // d_state
constexpr int L  = 64;    // block_len (last chunk)
constexpr int T0 = T - L; // 4032

__device__ __forceinline__ void fma2(unsigned long long& d,
                                     unsigned long long a,
                                     unsigned long long b) {
    asm("fma.rn.f32x2 %0, %1, %2, %0;" : "+l"(d) : "l"(a), "l"(b));
}

__global__ __launch_bounds__(256, 1)
void mamba_final_state_kernel(const float* __restrict__ X,
                              const float* __restrict__ A,
                              const float* __restrict__ Bm,
                              float* __restrict__ out) {
    const int bh    = blockIdx.x;      // 0..31  (b*16 + h)
    const int b     = bh >> 4;
    const int h     = bh & 15;
    const int ntile = blockIdx.y;      // 0..3, 32 n-columns each
    const int tid   = threadIdx.x;     // 256 threads

    const int lane  = tid & 31;
    const int wrp   = tid >> 5;        // 0..7
    const int p     = ((wrp & 1) << 5) | lane;  // warp-coalesced X column
    const int ng    = wrp >> 1;        // 0..3 (8 n's per thread)

    __shared__ float Bs[L][32];        // 8 KB, later scaled by w[l]
    __shared__ float wpart[L];
    __shared__ float wtot[2];
    __shared__ float wsh[L];

    // ---- issue ALL gmem loads up front ----

    // A for last chunk -> registers of threads 0..63
    float a = 0.f;
    if (tid < L)
        a = A[(size_t)(b * T + T0 + tid) * H + h];

    // X streamed to registers: thread owns column p; per-l warp load is a
    // coalesced 128B transaction. 64 LDG.32 per thread, stride 4 KB.
    const float* xcol = X + ((size_t)(b * T + T0) * H + h) * (size_t)P + p;
    float xr[L];
    #pragma unroll
    for (int l = 0; l < L; l++)
        xr[l] = xcol[(size_t)l * (H * P)];

    // B tile raw -> smem: 64x32 = 512 float4
    {
        const float* bbase = Bm + (size_t)(b * T + T0) * (H * N)
                                + (size_t)h * N + ntile * 32;
        #pragma unroll
        for (int it = 0; it < 2; it++) {
            int i  = tid + it * 256;   // 0..511
            int l  = i >> 3;           // 8 float4 per row
            int c4 = i & 7;
            float4 v = *reinterpret_cast<const float4*>(
                bbase + (size_t)l * (H * N) + c4 * 4);
            *reinterpret_cast<float4*>(&Bs[l][c4 * 4]) = v;
        }
    }

    // ---- warp-shfl inclusive scan of A (overlaps the loads) ----
    if (tid < L) {
        float c = a;
        #pragma unroll
        for (int off = 1; off < 32; off <<= 1) {
            float t = __shfl_up_sync(0xffffffffu, c, off);
            if (lane >= off) c += t;
        }
        wpart[tid] = c;
        if (lane == 31) wtot[tid >> 5] = c;
    }
    __syncthreads();

    // ---- w[l] = exp(2*S - cumsum_incl[l]) ----
    if (tid < L) {
        float tot0 = wtot[0];
        float S    = tot0 + wtot[1];
        float cc   = wpart[tid] + (tid >= 32 ? tot0 : 0.f);
        wsh[tid]   = __expf(2.f * S - cc);
    }
    __syncthreads();

    // ---- fold w into B rows in place (512 float4) ----
    {
        #pragma unroll
        for (int it = 0; it < 2; it++) {
            int i   = tid + it * 256;
            int l   = i >> 3;
            int c4  = i & 7;
            float wl = wsh[l];
            float4 v = *reinterpret_cast<float4*>(&Bs[l][c4 * 4]);
            v.x *= wl; v.y *= wl; v.z *= wl; v.w *= wl;
            *reinterpret_cast<float4*>(&Bs[l][c4 * 4]) = v;
        }
    }
    __syncthreads();

    // ---- compute: thread -> (p, 8 consecutive n); X from regs, B broadcast ----
    unsigned long long acc0 = 0ull, acc1 = 0ull, acc2 = 0ull, acc3 = 0ull;

    #pragma unroll
    for (int l = 0; l < L; l++) {
        unsigned long long x2;
        asm("mov.b64 %0, {%1, %1};" : "=l"(x2) : "f"(xr[l]));
        const ulonglong2* bp =
            reinterpret_cast<const ulonglong2*>(&Bs[l][ng * 8]);  // 32B aligned
        ulonglong2 q0 = bp[0];                        // LDS.128 broadcast
        ulonglong2 q1 = bp[1];                        // LDS.128 broadcast
        fma2(acc0, x2, q0.x);
        fma2(acc1, x2, q0.y);
        fma2(acc2, x2, q1.x);
        fma2(acc3, x2, q1.y);
    }

    float* o = out + ((size_t)(bh * P + p)) * N + ntile * 32 + ng * 8;
    ulonglong2 s0; s0.x = acc0; s0.y = acc1;
    ulonglong2 s1; s1.x = acc2; s1.y = acc3;
    *reinterpret_cast<ulonglong2*>(o)     = s0;       // STG.128
    *reinterpret_cast<ulonglong2*>(o + 4) = s1;       // STG.128
}

} // namespace

extern "C" void kernel_launch(void* const* d_in, const int* in_sizes, int n_in,
                              void* d_out, int out_size) {
    const float* X = (const float*)d_in[0];  // (2, 4096, 16, 64)  f32
    const float* A = (const float*)d_in[1];  // (2, 4096, 16)      f32
    const float* B = (const float*)d_in[2];  // (2, 4096, 16, 128) f32
    float* out = (float*)d_out;              // (2, 16, 64, 128)   f32

    dim3 grid(32, 4);   // (b*h pairs, n-tiles of 32)
    mamba_final_state_kernel<<<grid, 256>>>(X, A, B, out);
}